// round 1
// baseline (speedup 1.0000x reference)
#include <cuda_runtime.h>

// AlarmworkRNN collapsed to a vector RNN:
// out[t] only depends on sequence row 2047 of the state, and the recurrence is
// row-independent, so we track only z1[1024], z2[1024] driven by x[t, 2047, :].
//
// Persistent kernel: 128 CTAs (single wave on 148 SMs), weights SMEM-resident,
// one global barrier per step (monotonic counter, reset by init kernel).

#define GRID  128
#define BLOCK 512
#define JPB   8          // layer-1/2 output columns per CTA (1024/128)
#define OPB   2          // output columns per CTA (256/128)
#define KEXT  1280       // 256 (x) + 1024 (state)
#define NSTEP 256

__device__ unsigned g_arrive;
__device__ float g_z1[2 * 1024];   // double-buffered z1
__device__ float g_z2[2 * 1024];   // double-buffered z2

__global__ void rnn_init_kernel() { g_arrive = 0u; }

__global__ __launch_bounds__(BLOCK, 1)
void rnn_persistent_kernel(const float* __restrict__ x,
                           const float* __restrict__ W_in1,
                           const float* __restrict__ b_in1,
                           const float* __restrict__ W_rec1,
                           const float* __restrict__ W_in2,
                           const float* __restrict__ b_in2,
                           const float* __restrict__ W_rec2,
                           const float* __restrict__ W_out,
                           const float* __restrict__ b_out,
                           float* __restrict__ out)
{
    extern __shared__ float sm[];
    float* ws1 = sm;                    // [JPB][KEXT]   layer1 weights (col-slices, K-contig)
    float* ws2 = ws1 + JPB * KEXT;      // [JPB][KEXT]   layer2 weights
    float* wso = ws2 + JPB * KEXT;      // [OPB][1024]   out weights
    float* e1  = wso + OPB * 1024;      // [KEXT]        [x | z1+z2]
    float* e2  = e1 + KEXT;             // [KEXT]        [x | z2]
    float* sz1 = e2 + KEXT;             // [1024]        z1 (previous step, for out GEMV)

    const int tid  = threadIdx.x;
    const int warp = tid >> 5;
    const int lane = tid & 31;
    const int j0   = blockIdx.x * JPB;  // layer output column base
    const int o0   = blockIdx.x * OPB;  // out column base

    const int role = warp >> 3;         // 0: layer1 warps (0..7), 1: layer2 warps (8..15)
    const int lw   = warp & 7;          // output index within this CTA's slice

    // ---- One-time weight preload into SMEM (each CTA owns disjoint columns) ----
    for (int idx = tid; idx < JPB * KEXT; idx += BLOCK) {
        int k = idx >> 3;               // 0..1279
        int w = idx & 7;                // 0..7
        int j = j0 + w;
        ws1[w * KEXT + k] = (k < 256) ? W_in1[k * 1024 + j]
                                      : W_rec1[(k - 256) * 1024 + j];
        ws2[w * KEXT + k] = (k < 256) ? W_in2[k * 1024 + j]
                                      : W_rec2[(k - 256) * 1024 + j];
    }
    for (int idx = tid; idx < OPB * 1024; idx += BLOCK) {
        int j = idx >> 1;
        int c = idx & 1;
        wso[c * 1024 + j] = W_out[j * 256 + o0 + c];
    }
    const float bias = (role == 0) ? b_in1[j0 + lw] : b_in2[j0 + lw];
    const float bo   = (warp < OPB) ? b_out[o0 + warp] : 0.0f;
    __syncthreads();

    const float* wsl = ((role == 0) ? ws1 : ws2) + lw * KEXT;

    // ---- Step loop. Iteration t computes z(t) and out[t-1] (pipelined). ----
    // t == NSTEP iteration only computes out[NSTEP-1].
    for (int t = 0; t <= NSTEP; t++) {
        const int pr = t & 1;           // read buffer (written by step t-1)
        const int pw = pr ^ 1;          // write buffer

        // Phase A: stage x row and state vectors into SMEM
        if (t < NSTEP && tid < 256) {
            float v = x[((size_t)t * 2048 + 2047) * 256 + tid];
            e1[tid] = v;
            e2[tid] = v;
        }
        if (t == 0) {
            for (int j = tid; j < 1024; j += BLOCK) {
                e1[256 + j] = 0.0f; e2[256 + j] = 0.0f; sz1[j] = 0.0f;
            }
        } else {
            for (int j = tid; j < 1024; j += BLOCK) {
                float a = g_z1[pr * 1024 + j];
                float b = g_z2[pr * 1024 + j];
                e1[256 + j] = a + b;    // z12 = z1 + z2
                e2[256 + j] = b;        // z2
                sz1[j]      = a;        // z1 (for pipelined out GEMV)
            }
        }
        __syncthreads();

        // Phase B: GEMVs
        if (t < NSTEP) {
            const bool compute = (role == 0) || ((t & 1) == 0);
            if (compute) {
                const float4* wv = (const float4*)wsl;
                const float4* ev = (const float4*)((role == 0) ? e1 : e2);
                float acc = 0.0f;
                #pragma unroll
                for (int i = 0; i < KEXT / 128; i++) {
                    float4 wq = wv[lane + 32 * i];
                    float4 eq = ev[lane + 32 * i];
                    acc += wq.x * eq.x + wq.y * eq.y + wq.z * eq.z + wq.w * eq.w;
                }
                #pragma unroll
                for (int off = 16; off; off >>= 1)
                    acc += __shfl_xor_sync(0xffffffffu, acc, off);
                if (lane == 0) {
                    float v = tanhf(acc + bias);
                    if (role == 0) g_z1[pw * 1024 + j0 + lw] = v;
                    else           g_z2[pw * 1024 + j0 + lw] = v;
                }
            } else {
                // odd step: layer2 holds previous state
                if (lane == 0) g_z2[pw * 1024 + j0 + lw] = e2[256 + j0 + lw];
            }
        }

        // out[t-1] from z1 of previous step (sz1)
        if (t >= 1 && warp < OPB) {
            const float4* wv = (const float4*)(wso + warp * 1024);
            const float4* zv = (const float4*)sz1;
            float acc = 0.0f;
            #pragma unroll
            for (int i = 0; i < 1024 / 128; i++) {
                float4 wq = wv[lane + 32 * i];
                float4 zq = zv[lane + 32 * i];
                acc += wq.x * zq.x + wq.y * zq.y + wq.z * zq.z + wq.w * zq.w;
            }
            #pragma unroll
            for (int off = 16; off; off >>= 1)
                acc += __shfl_xor_sync(0xffffffffu, acc, off);
            if (lane == 0)
                out[(size_t)(t - 1) * 256 + o0 + warp] = tanhf(acc + bo);
        }

        __syncthreads();   // SMEM (e1/e2/sz1) safe to overwrite next iteration

        // Device-wide barrier (monotonic counter; init kernel zeroes it per launch)
        if (t < NSTEP) {
            if (tid == 0) {
                __threadfence();
                atomicAdd(&g_arrive, 1u);
                const unsigned target = (unsigned)(t + 1) * GRID;
                while (*(volatile unsigned*)&g_arrive < target) { }
                __threadfence();
            }
            __syncthreads();
        }
    }
}

extern "C" void kernel_launch(void* const* d_in, const int* in_sizes, int n_in,
                              void* d_out, int out_size) {
    (void)in_sizes; (void)n_in; (void)out_size;
    const float* x      = (const float*)d_in[0];
    const float* W_in1  = (const float*)d_in[1];
    const float* b_in1  = (const float*)d_in[2];
    const float* W_rec1 = (const float*)d_in[3];
    const float* W_in2  = (const float*)d_in[4];
    const float* b_in2  = (const float*)d_in[5];
    const float* W_rec2 = (const float*)d_in[6];
    const float* W_out  = (const float*)d_in[7];
    const float* b_out  = (const float*)d_in[8];
    float* out = (float*)d_out;

    const size_t smem_bytes =
        (size_t)(JPB * KEXT * 2 + OPB * 1024 + KEXT * 2 + 1024) * sizeof(float);

    cudaFuncSetAttribute(rnn_persistent_kernel,
                         cudaFuncAttributeMaxDynamicSharedMemorySize,
                         (int)smem_bytes);

    rnn_init_kernel<<<1, 1>>>();
    rnn_persistent_kernel<<<GRID, BLOCK, smem_bytes>>>(
        x, W_in1, b_in1, W_rec1, W_in2, b_in2, W_rec2, W_out, b_out, out);
}

// round 2
// speedup vs baseline: 1.3438x; 1.3438x over previous
#include <cuda_runtime.h>

// AlarmworkRNN collapsed to a vector RNN (only sequence row 2047 matters).
// Round 2: weights register-resident, x prefetched one step ahead,
// release/acquire global barrier with out-GEMV + prefetch hidden in the wait.

#define GRID  128
#define BLOCK 512
#define JPB   8          // layer-1/2 output columns per CTA (1024/128)
#define OPB   2          // final-output columns per CTA (256/128)
#define KEXT  1280       // 256 (x) + 1024 (state)
#define NWQ   (KEXT/128) // float4 chunks per lane = 10
#define NSTEP 256

__device__ unsigned g_arrive;
__device__ float g_z1[2 * 1024];
__device__ float g_z2[2 * 1024];

__global__ void rnn_init_kernel() { g_arrive = 0u; }

__device__ __forceinline__ void barrier_arrive_release(unsigned* p) {
    asm volatile("red.release.gpu.global.add.u32 [%0], %1;"
                 :: "l"(p), "r"(1u) : "memory");
}
__device__ __forceinline__ unsigned ld_acquire_gpu(unsigned* p) {
    unsigned v;
    asm volatile("ld.acquire.gpu.global.u32 %0, [%1];"
                 : "=r"(v) : "l"(p) : "memory");
    return v;
}

__global__ __launch_bounds__(BLOCK, 1)
void rnn_persistent_kernel(const float* __restrict__ x,
                           const float* __restrict__ W_in1,
                           const float* __restrict__ b_in1,
                           const float* __restrict__ W_rec1,
                           const float* __restrict__ W_in2,
                           const float* __restrict__ b_in2,
                           const float* __restrict__ W_rec2,
                           const float* __restrict__ W_out,
                           const float* __restrict__ b_out,
                           float* __restrict__ out)
{
    extern __shared__ float sm[];
    float* wso   = sm;                  // [OPB][1024] out weights (persistent)
    float* e1    = wso + OPB * 1024;    // [KEXT]  [x | z1+z2]
    float* e2    = e1 + KEXT;           // [KEXT]  [x | z2]
    float* sz1   = e2 + KEXT;           // [1024]  z1 of previous step
    float* stage = sz1 + 1024;          // [JPB*KEXT] weight staging (preload only)

    const int tid  = threadIdx.x;
    const int warp = tid >> 5;
    const int lane = tid & 31;
    const int j0   = blockIdx.x * JPB;
    const int o0   = blockIdx.x * OPB;

    const int role = warp >> 3;         // 0: layer1 warps, 1: layer2 warps
    const int lw   = warp & 7;

    // ---- Preload: out weights to SMEM, layer weights to registers ----
    for (int idx = tid; idx < OPB * 1024; idx += BLOCK) {
        int j = idx >> 1, c = idx & 1;
        wso[c * 1024 + j] = W_out[j * 256 + o0 + c];
    }

    float wreg[4 * NWQ];
    // round 0: layer1, round 1: layer2 (same staging buffer)
    for (int round = 0; round < 2; round++) {
        for (int idx = tid; idx < JPB * KEXT; idx += BLOCK) {
            int k = idx >> 3, w = idx & 7, j = j0 + w;
            float v;
            if (round == 0)
                v = (k < 256) ? W_in1[k * 1024 + j] : W_rec1[(k - 256) * 1024 + j];
            else
                v = (k < 256) ? W_in2[k * 1024 + j] : W_rec2[(k - 256) * 1024 + j];
            stage[w * KEXT + k] = v;
        }
        __syncthreads();
        if (role == round) {
            const float4* src = (const float4*)(stage + lw * KEXT);
            #pragma unroll
            for (int i = 0; i < NWQ; i++) {
                float4 q = src[lane + 32 * i];
                wreg[4*i+0] = q.x; wreg[4*i+1] = q.y;
                wreg[4*i+2] = q.z; wreg[4*i+3] = q.w;
            }
        }
        __syncthreads();
    }

    const float bias = (role == 0) ? b_in1[j0 + lw] : b_in2[j0 + lw];
    const float bo   = (warp < OPB) ? b_out[o0 + warp] : 0.0f;

    // Prefetch x row for t = 0
    float xreg = 0.0f;
    if (tid < 256) xreg = x[(size_t)2047 * 256 + tid];

    // ---- Step loop: iteration t computes z(t) and out[t-1] ----
    for (int t = 0; t <= NSTEP; t++) {
        const int pr = t & 1;
        const int pw = pr ^ 1;

        // Phase A: stage inputs/state into SMEM
        if (t < NSTEP && tid < 256) {
            e1[tid] = xreg;
            e2[tid] = xreg;
        }
        if (t == 0) {
            for (int j = tid; j < 1024; j += BLOCK) {
                e1[256 + j] = 0.0f; e2[256 + j] = 0.0f; sz1[j] = 0.0f;
            }
        } else {
            for (int j = tid; j < 1024; j += BLOCK) {
                float a = g_z1[pr * 1024 + j];
                float b = g_z2[pr * 1024 + j];
                e1[256 + j] = a + b;
                e2[256 + j] = b;
                sz1[j]      = a;
            }
        }
        __syncthreads();

        // Phase B: layer GEMVs (weights in registers, e from SMEM)
        if (t < NSTEP) {
            const bool compute = (role == 0) || ((t & 1) == 0);
            if (compute) {
                const float4* ev = (const float4*)((role == 0) ? e1 : e2);
                float acc = 0.0f;
                #pragma unroll
                for (int i = 0; i < NWQ; i++) {
                    float4 q = ev[lane + 32 * i];
                    acc += wreg[4*i+0] * q.x + wreg[4*i+1] * q.y
                         + wreg[4*i+2] * q.z + wreg[4*i+3] * q.w;
                }
                #pragma unroll
                for (int off = 16; off; off >>= 1)
                    acc += __shfl_xor_sync(0xffffffffu, acc, off);
                if (lane == 0) {
                    float v = tanhf(acc + bias);
                    if (role == 0) g_z1[pw * 1024 + j0 + lw] = v;
                    else           g_z2[pw * 1024 + j0 + lw] = v;
                }
            } else {
                if (lane == 0) g_z2[pw * 1024 + j0 + lw] = e2[256 + j0 + lw];
            }
        }
        __syncthreads();   // all state writes done CTA-wide

        // Arrive early; hide out-GEMV + x prefetch in the wait window
        if (t < NSTEP && tid == 0)
            barrier_arrive_release(&g_arrive);

        if (t + 1 < NSTEP && tid < 256)
            xreg = x[((size_t)(t + 1) * 2048 + 2047) * 256 + tid];

        if (t >= 1 && warp < OPB) {
            const float4* wv = (const float4*)(wso + warp * 1024);
            const float4* zv = (const float4*)sz1;
            float acc = 0.0f;
            #pragma unroll
            for (int i = 0; i < 8; i++) {
                float4 wq = wv[lane + 32 * i];
                float4 zq = zv[lane + 32 * i];
                acc += wq.x * zq.x + wq.y * zq.y + wq.z * zq.z + wq.w * zq.w;
            }
            #pragma unroll
            for (int off = 16; off; off >>= 1)
                acc += __shfl_xor_sync(0xffffffffu, acc, off);
            if (lane == 0)
                out[(size_t)(t - 1) * 256 + o0 + warp] = tanhf(acc + bo);
        }

        // Wait for all CTAs
        if (t < NSTEP) {
            if (tid == 0) {
                const unsigned target = (unsigned)(t + 1) * GRID;
                while (ld_acquire_gpu(&g_arrive) < target) { }
            }
            __syncthreads();
        }
    }
}

extern "C" void kernel_launch(void* const* d_in, const int* in_sizes, int n_in,
                              void* d_out, int out_size) {
    (void)in_sizes; (void)n_in; (void)out_size;
    const float* x      = (const float*)d_in[0];
    const float* W_in1  = (const float*)d_in[1];
    const float* b_in1  = (const float*)d_in[2];
    const float* W_rec1 = (const float*)d_in[3];
    const float* W_in2  = (const float*)d_in[4];
    const float* b_in2  = (const float*)d_in[5];
    const float* W_rec2 = (const float*)d_in[6];
    const float* W_out  = (const float*)d_in[7];
    const float* b_out  = (const float*)d_in[8];
    float* out = (float*)d_out;

    const size_t smem_bytes =
        (size_t)(OPB * 1024 + KEXT * 2 + 1024 + JPB * KEXT) * sizeof(float);

    cudaFuncSetAttribute(rnn_persistent_kernel,
                         cudaFuncAttributeMaxDynamicSharedMemorySize,
                         (int)smem_bytes);

    rnn_init_kernel<<<1, 1>>>();
    rnn_persistent_kernel<<<GRID, BLOCK, smem_bytes>>>(
        x, W_in1, b_in1, W_rec1, W_in2, b_in2, W_rec2, W_out, b_out, out);
}

// round 3
// speedup vs baseline: 1.4801x; 1.1014x over previous
#include <cuda_runtime.h>

// AlarmworkRNN collapsed to a vector RNN (only sequence row 2047 matters).
// Round 3: dedicated barrier thread, broadcast-lane GEMV (8 outputs/warp over
// a 160-wide K slice, 8x less SMEM crossbar traffic), float2-packed state.

#define GRID  128
#define BLOCK 512
#define KEXT  1280       // 256 (x) + 1024 (state)
#define NSTEP 256
#define BAR_TID 416      // warp 13 lane 0: no out-GEMV, no final reduce

__device__ unsigned g_arrive;
__device__ float2 g_z[2 * 1024];   // double-buffered (z1, z2)

__global__ void rnn_init_kernel() { g_arrive = 0u; }

__device__ __forceinline__ void barrier_arrive_release(unsigned* p) {
    asm volatile("red.release.gpu.global.add.u32 [%0], %1;"
                 :: "l"(p), "r"(1u) : "memory");
}
__device__ __forceinline__ unsigned ld_acquire_gpu(unsigned* p) {
    unsigned v;
    asm volatile("ld.acquire.gpu.global.u32 %0, [%1];"
                 : "=r"(v) : "l"(p) : "memory");
    return v;
}

__global__ __launch_bounds__(BLOCK, 1)
void rnn_persistent_kernel(const float* __restrict__ x,
                           const float* __restrict__ W_in1,
                           const float* __restrict__ b_in1,
                           const float* __restrict__ W_rec1,
                           const float* __restrict__ W_in2,
                           const float* __restrict__ b_in2,
                           const float* __restrict__ W_rec2,
                           const float* __restrict__ W_out,
                           const float* __restrict__ b_out,
                           float* __restrict__ out)
{
    extern __shared__ float sm[];
    float* wso   = sm;                  // [2][1024] out weights
    float* e1    = wso + 2048;          // [KEXT]  [x | z1+z2]
    float* e2    = e1 + KEXT;           // [KEXT]  [x | z2]
    float* sz1   = e2 + KEXT;           // [1024]  z1 of previous step
    float* redp  = sz1 + 1024;          // [2][8][8] cross-warp partials
    float* sbias = redp + 128;          // [2][8]
    float* stage = sbias + 16;          // [8*KEXT] weight staging (preload only)

    const int tid  = threadIdx.x;
    const int warp = tid >> 5;
    const int lane = tid & 31;
    const int j0   = blockIdx.x * 8;    // layer output column base
    const int o0   = blockIdx.x * 2;    // final output column base

    const int role = warp >> 3;         // 0: layer1 warps 0-7, 1: layer2 warps 8-15
    const int w8   = warp & 7;          // K-slice index within role
    const int o_l  = lane >> 2;         // output handled by this lane (0..7)
    const int g_l  = lane & 3;          // k-group within output (0..3)

    // ---- Preload ----
    for (int idx = tid; idx < 2048; idx += BLOCK) {
        int j = idx >> 1, c = idx & 1;
        wso[c * 1024 + j] = W_out[j * 256 + o0 + c];
    }
    if (tid < 8)            sbias[tid]     = b_in1[j0 + tid];
    else if (tid < 16)      sbias[tid]     = b_in2[j0 + tid - 8];

    float wreg[40];   // this lane's weights: output o_l, k in [w8*160+g_l*40, +40)
    for (int round = 0; round < 2; round++) {
        for (int idx = tid; idx < 8 * KEXT; idx += BLOCK) {
            int k = idx >> 3, o = idx & 7, j = j0 + o;
            float v;
            if (round == 0)
                v = (k < 256) ? W_in1[k * 1024 + j] : W_rec1[(k - 256) * 1024 + j];
            else
                v = (k < 256) ? W_in2[k * 1024 + j] : W_rec2[(k - 256) * 1024 + j];
            stage[o * KEXT + k] = v;
        }
        __syncthreads();
        if (role == round) {
            const float* src = stage + o_l * KEXT + w8 * 160 + g_l * 40;
            #pragma unroll
            for (int i = 0; i < 40; i++) wreg[i] = src[i];
        }
        __syncthreads();
    }

    const float bo = (warp < 2) ? b_out[o0 + warp] : 0.0f;

    // Prefetch x row for t = 0 (warps 8-15 hold x in registers)
    float xreg = 0.0f;
    if (tid >= 256) xreg = x[(size_t)2047 * 256 + (tid - 256)];

    // ---- Step loop: iteration t computes z(t) and out[t-1] ----
    for (int t = 0; t <= NSTEP; t++) {
        const int pr = t & 1;
        const int pw = pr ^ 1;

        // Phase A: stage x + state into SMEM
        if (t < NSTEP && tid >= 256) {
            e1[tid - 256] = xreg;
            e2[tid - 256] = xreg;
        }
        if (t == 0) {
            for (int j = tid; j < 1024; j += BLOCK) {
                e1[256 + j] = 0.0f; e2[256 + j] = 0.0f; sz1[j] = 0.0f;
            }
        } else {
            for (int j = tid; j < 1024; j += BLOCK) {
                float2 zz = g_z[pr * 1024 + j];
                e1[256 + j] = zz.x + zz.y;
                e2[256 + j] = zz.y;
                sz1[j]      = zz.x;
            }
        }
        __syncthreads();

        // Phase B: GEMV partials (broadcast-lane layout)
        if (t < NSTEP && ((role == 0) || ((t & 1) == 0))) {
            const float* ev = (role == 0) ? e1 : e2;
            const float4* evq = (const float4*)(ev + w8 * 160 + g_l * 40);
            float a0 = 0.0f, a1 = 0.0f;
            #pragma unroll
            for (int i = 0; i < 10; i++) {
                float4 q = evq[i];
                a0 += wreg[4*i+0] * q.x + wreg[4*i+1] * q.y;
                a1 += wreg[4*i+2] * q.z + wreg[4*i+3] * q.w;
            }
            float acc = a0 + a1;
            acc += __shfl_xor_sync(0xffffffffu, acc, 1);
            acc += __shfl_xor_sync(0xffffffffu, acc, 2);
            if (g_l == 0) redp[role * 64 + o_l * 8 + w8] = acc;
        }
        __syncthreads();

        // Phase C: cross-warp reduce + tanh + state publish (warps 14, 15)
        if (t < NSTEP && warp >= 14) {
            const int r = warp - 14;          // 0 = layer1, 1 = layer2
            float v;
            if ((r == 0) || ((t & 1) == 0)) {
                const float2 p = *(const float2*)(redp + r * 64 + o_l * 8 + 2 * g_l);
                v = p.x + p.y;
                v += __shfl_xor_sync(0xffffffffu, v, 1);
                v += __shfl_xor_sync(0xffffffffu, v, 2);
                v = tanhf(v + sbias[r * 8 + o_l]);
            } else {
                v = e2[256 + j0 + o_l];        // odd step: layer2 holds
            }
            if (g_l == 0) {
                if (r == 0) g_z[pw * 1024 + j0 + o_l].x = v;
                else        g_z[pw * 1024 + j0 + o_l].y = v;
            }
        }
        __syncthreads();

        // Arrive (dedicated thread), then hide out-GEMV + prefetch in the wait
        if (t < NSTEP && tid == BAR_TID)
            barrier_arrive_release(&g_arrive);

        if (t + 1 < NSTEP && tid >= 256)
            xreg = x[((size_t)(t + 1) * 2048 + 2047) * 256 + (tid - 256)];

        if (t >= 1 && warp < 2) {
            const float4* wv = (const float4*)(wso + warp * 1024);
            const float4* zv = (const float4*)sz1;
            float acc = 0.0f;
            #pragma unroll
            for (int i = 0; i < 8; i++) {
                float4 wq = wv[lane + 32 * i];
                float4 zq = zv[lane + 32 * i];
                acc += wq.x * zq.x + wq.y * zq.y + wq.z * zq.z + wq.w * zq.w;
            }
            #pragma unroll
            for (int off = 16; off; off >>= 1)
                acc += __shfl_xor_sync(0xffffffffu, acc, off);
            if (lane == 0)
                out[(size_t)(t - 1) * 256 + o0 + warp] = tanhf(acc + bo);
        }

        if (t < NSTEP) {
            if (tid == BAR_TID) {
                const unsigned target = (unsigned)(t + 1) * GRID;
                while (ld_acquire_gpu(&g_arrive) < target) { }
            }
            __syncthreads();
        }
    }
}

extern "C" void kernel_launch(void* const* d_in, const int* in_sizes, int n_in,
                              void* d_out, int out_size) {
    (void)in_sizes; (void)n_in; (void)out_size;
    const float* x      = (const float*)d_in[0];
    const float* W_in1  = (const float*)d_in[1];
    const float* b_in1  = (const float*)d_in[2];
    const float* W_rec1 = (const float*)d_in[3];
    const float* W_in2  = (const float*)d_in[4];
    const float* b_in2  = (const float*)d_in[5];
    const float* W_rec2 = (const float*)d_in[6];
    const float* W_out  = (const float*)d_in[7];
    const float* b_out  = (const float*)d_in[8];
    float* out = (float*)d_out;

    const size_t smem_bytes =
        (size_t)(2048 + KEXT * 2 + 1024 + 128 + 16 + 8 * KEXT) * sizeof(float);

    cudaFuncSetAttribute(rnn_persistent_kernel,
                         cudaFuncAttributeMaxDynamicSharedMemorySize,
                         (int)smem_bytes);

    rnn_init_kernel<<<1, 1>>>();
    rnn_persistent_kernel<<<GRID, BLOCK, smem_bytes>>>(
        x, W_in1, b_in1, W_rec1, W_in2, b_in2, W_rec2, W_out, b_out, out);
}